// round 15
// baseline (speedup 1.0000x reference)
#include <cuda_runtime.h>

#define NCLS 19
#define HW_   (512*1024)        // 2^19
#define NPIX  (4*HW_)           // 2,097,152
#define NPIX4 (NPIX/4)          // 524,288
#define GRID_L 4736             // 8 waves of 4 CTA/SM (straggler smoothing)
#define GRID_T 592              // tail: 4 CTA/SM co-resident (spin-safe)
#define QPT    4                // tail quads/thread: 592*256*4 >= NPIX4
#define TB    256
#define INV   0xFFFFFFFFu

// ---- static scratch (zero-init at load; self-cleaned each call) ----
__device__ float    g_loss[NPIX];        // 8 MB
__device__ unsigned g_compact[NPIX];     // compact in-bin list
__device__ unsigned g_ccount;
__device__ unsigned g_hist0[4096];
__device__ unsigned g_hist1[4096];
__device__ unsigned g_cnt2[256];
__device__ float    g_sum2[256];
__device__ double   g_sumHi;
__device__ unsigned g_cntHi;
__device__ unsigned g_pref0p1, g_pref01p1, g_k1, g_k2;   // prefix+1; 0 = invalid
__device__ unsigned g_done0, g_done1, g_done2, g_flag1;

// ------------------------------------------------------------------
// Descending scan over a 4096-bin histogram; winning thread writes the
// (bin, rank) into shared outputs. 256 threads, 16 bins each.
__device__ void scan4096(const unsigned* __restrict__ hist, unsigned k,
                         unsigned* ss, unsigned* out_bin, unsigned* out_r,
                         bool derive_k) {
    int t = threadIdx.x;
    unsigned cnt[16]; unsigned myv = 0;
    #pragma unroll
    for (int i = 0; i < 16; i++) { cnt[i] = __ldcg(&hist[4095 - (t * 16 + i)]); myv += cnt[i]; }
    ss[t] = myv; __syncthreads();
    for (int off = 1; off < 256; off <<= 1) {
        unsigned x = (t >= off) ? ss[t - off] : 0u;
        __syncthreads(); ss[t] += x; __syncthreads();
    }
    if (derive_k) {
        unsigned total = ss[255];          // uniform
        if (total == 0) return;            // *out_bin stays INV
        unsigned nk = (unsigned)(0.7f * (float)total);
        if (nk < 100000u) nk = 100000u;
        if (nk > total)   nk = total;
        k = nk;
    }
    unsigned hi = ss[t], lo = hi - myv;
    if (k > lo && k <= hi) {               // exactly one thread wins
        unsigned cum = lo;
        #pragma unroll
        for (int i = 0; i < 16; i++) {
            cum += cnt[i];
            if (k <= cum) {
                *out_bin = 4095u - (t * 16 + i);
                *out_r   = k - (cum - cnt[i]);
                break;
            }
        }
    }
}

// ------------------------------------------------------------------
// Pass A: streaming NLL with v[19] BATCHED loads (MLP=19, 64-reg budget),
// multi-wave grid. hist0 + fused scan0 + self-clean by last block.
__global__ void __launch_bounds__(TB, 4) k_loss(const float* __restrict__ logits,
                                                const void* __restrict__ tgt_raw) {
    __shared__ unsigned sh[4096];
    __shared__ unsigned s_ss[256];
    __shared__ unsigned s_bin, s_r;
    __shared__ bool     s_last;
    int t = threadIdx.x;
    for (int i = t; i < 4096; i += TB) sh[i] = 0;
    __syncthreads();

    // dtype detection (uniform, cached)
    const long long* tdet = (const long long*)tgt_raw;
    int tmode = 1;
    #pragma unroll
    for (int i = 0; i < 8; i++) {
        long long x = tdet[i];
        if (x < 0 || x >= (long long)NCLS) tmode = 0;
    }
    const long long* t64 = (const long long*)tgt_raw;
    const int*       t32 = (const int*)tgt_raw;

    int stride = GRID_L * TB;
    for (int p = blockIdx.x * TB + t; p < NPIX; p += stride) {
        int n  = p >> 19;
        int hw = p & (HW_ - 1);
        const float* base = logits + (size_t)n * (NCLS * (size_t)HW_) + hw;
        int tt = tmode ? (int)__ldg(t64 + p) : __ldg(t32 + p);

        float v[NCLS];                     // 19 independent loads, batched
        #pragma unroll
        for (int c = 0; c < NCLS; c++) v[c] = __ldg(base + (size_t)c * HW_);
        float xt = __ldg(base + (size_t)tt * HW_);   // dup of one v load: L1 hit

        float s = 0.f;
        #pragma unroll
        for (int c = 0; c < NCLS; c++) s += __expf(v[c]);

        float l = __logf(s) - xt;
        g_loss[p] = l;
        if (l > 0.f) atomicAdd(&sh[__float_as_uint(l) >> 20], 1u);
    }
    __syncthreads();
    for (int i = t; i < 4096; i += TB) {
        unsigned c = sh[i];
        if (c) atomicAdd(&g_hist0[i], c);
    }
    __threadfence();
    __syncthreads();                        // all hist0 atomics issued
    if (t == 0) s_last = (atomicAdd(&g_done0, 1u) == GRID_L - 1);
    __syncthreads();
    if (!s_last) return;

    // ---- fused scan0 (last block) + self-clean ----
    if (t == 0) { s_bin = INV; s_r = 0; }
    __syncthreads();
    scan4096(g_hist0, 0, s_ss, &s_bin, &s_r, true);
    __syncthreads();
    if (t == 0 && s_bin != INV) { g_pref0p1 = s_bin + 1u; g_k1 = s_r; }
    for (int i = t; i < 4096; i += TB) g_hist0[i] = 0;
    if (t == 0) g_done0 = 0;
}

// ------------------------------------------------------------------
// Tail: ONE co-resident kernel. Phase 1: batched read of the loss array;
// above-bin -> register sums; in-bin -> smem hist1 + compact. Rendezvous:
// scan1 by last block, flag broadcast. Phase 2: byte phase over the tiny
// compact list. Rendezvous: final mean + full state reset.
__global__ void __launch_bounds__(TB, 4) k_tail(float* __restrict__ out) {
    __shared__ unsigned sh[4096];
    __shared__ unsigned s_buf[4096];        // block covers exactly 4096 pixels
    __shared__ unsigned s_ss[256];
    __shared__ double   s_rd[256];
    __shared__ unsigned s_rc[256];
    __shared__ unsigned s_bin, s_r, s_cnt, s_base;
    __shared__ bool     s_last;
    int t = threadIdx.x;
    for (int i = t; i < 4096; i += TB) sh[i] = 0;
    if (t == 0) s_cnt = 0;
    __syncthreads();

    unsigned p0p1 = g_pref0p1;
    const uint4* lv = (const uint4*)g_loss;
    const int stride = GRID_T * TB;
    const int q0 = blockIdx.x * TB + t;

    uint4 q[QPT]; bool qok[QPT];
    #pragma unroll
    for (int i = 0; i < QPT; i++) {
        int qq = q0 + i * stride;
        qok[i] = (qq < NPIX4);
        q[i] = qok[i] ? __ldg(lv + qq) : make_uint4(0, 0, 0, 0);
    }

    float fHi = 0.f; unsigned cHi = 0;
    if (p0p1 != 0u) {
        unsigned pref0 = p0p1 - 1u;
        #pragma unroll
        for (int i = 0; i < QPT; i++) {
            if (!qok[i]) continue;
            #pragma unroll
            for (int j = 0; j < 4; j++) {
                unsigned bb = (j == 0) ? q[i].x : (j == 1) ? q[i].y : (j == 2) ? q[i].z : q[i].w;
                if ((int)bb > 0) {
                    unsigned b20 = bb >> 20;
                    if (b20 > pref0) { fHi += __uint_as_float(bb); cHi++; }
                    else if (b20 == pref0) {
                        atomicAdd(&sh[(bb >> 8) & 0xFFFu], 1u);
                        unsigned idx = atomicAdd(&s_cnt, 1u);
                        s_buf[idx] = bb;
                    }
                }
            }
        }
    } else {
        // no valid pixels: sum everything for the fallback mean
        #pragma unroll
        for (int i = 0; i < QPT; i++)
            fHi += __uint_as_float(q[i].x) + __uint_as_float(q[i].y)
                 + __uint_as_float(q[i].z) + __uint_as_float(q[i].w);
    }
    __syncthreads();                        // s_cnt, sh final

    if (t == 0 && p0p1 != 0u && s_cnt) s_base = atomicAdd(&g_ccount, s_cnt);
    s_rd[t] = (double)fHi; s_rc[t] = cHi;
    __syncthreads();                        // s_base visible

    if (p0p1 != 0u) {
        for (int i = t; i < 4096; i += TB) {
            unsigned c = sh[i];
            if (c) atomicAdd(&g_hist1[i], c);
        }
        for (unsigned i = t; i < s_cnt; i += TB) g_compact[s_base + i] = s_buf[i];
    }
    for (int off = 128; off > 0; off >>= 1) {
        if (t < off) { s_rd[t] += s_rd[t + off]; s_rc[t] += s_rc[t + off]; }
        __syncthreads();
    }
    if (t == 0) {
        atomicAdd(&g_sumHi, s_rd[0]);
        if (s_rc[0]) atomicAdd(&g_cntHi, s_rc[0]);
    }
    __threadfence();
    __syncthreads();                        // all phase-1 global work issued
    if (t == 0) s_last = (atomicAdd(&g_done1, 1u) == GRID_T - 1);
    __syncthreads();

    // ---- scan1 by last-arriving block; flag releases everyone ----
    if (s_last) {
        if (t == 0) { s_bin = INV; s_r = 0; }
        __syncthreads();
        if (p0p1 != 0u) {
            scan4096(g_hist1, __ldcg(&g_k1), s_ss, &s_bin, &s_r, false);
            __syncthreads();
        }
        if (t == 0) {
            if (p0p1 != 0u && s_bin != INV) {
                g_pref01p1 = (((p0p1 - 1u) << 12) | s_bin) + 1u;
                g_k2 = s_r;
            }
            __threadfence();
            atomicExch(&g_flag1, 1u);
        }
    }
    if (t == 0) { while (*(volatile unsigned*)&g_flag1 == 0u) __nanosleep(64); }
    __syncthreads();
    __threadfence();
    unsigned p01p1 = *(volatile unsigned*)&g_pref01p1;

    // ---- phase 2: byte phase over the compact list (L2-resident) ----
    unsigned* s_cnt2 = sh;                  // reuse sh[0..255]
    float*    s_fs2  = (float*)(sh + 256);  // sh[256..511]
    for (int i = t; i < 256; i += TB) { s_cnt2[i] = 0; s_fs2[i] = 0.f; }
    __syncthreads();

    float fHi2 = 0.f; unsigned cHi2 = 0;
    if (p01p1 != 0u) {
        unsigned n = *(volatile unsigned*)&g_ccount;
        unsigned pref1 = (p01p1 - 1u) & 0xFFFu;
        for (unsigned i = blockIdx.x * TB + t; i < n; i += GRID_T * TB) {
            unsigned bb = __ldcg(&g_compact[i]);    // all match pref0 already
            unsigned mid = (bb >> 8) & 0xFFFu;
            if (mid > pref1) { fHi2 += __uint_as_float(bb); cHi2++; }
            else if (mid == pref1) {
                atomicAdd(&s_cnt2[bb & 0xFFu], 1u);
                atomicAdd(&s_fs2[bb & 0xFFu], __uint_as_float(bb));
            }
        }
    }
    s_rd[t] = (double)fHi2; s_rc[t] = cHi2;
    __syncthreads();
    for (int off = 128; off > 0; off >>= 1) {
        if (t < off) { s_rd[t] += s_rd[t + off]; s_rc[t] += s_rc[t + off]; }
        __syncthreads();
    }
    if (t == 0) {
        atomicAdd(&g_sumHi, s_rd[0]);
        if (s_rc[0]) atomicAdd(&g_cntHi, s_rc[0]);
    }
    for (int i = t; i < 256; i += TB) {
        if (s_cnt2[i]) { atomicAdd(&g_cnt2[i], s_cnt2[i]); atomicAdd(&g_sum2[i], s_fs2[i]); }
    }
    __threadfence();
    __syncthreads();                        // all phase-2 atomics issued
    if (t == 0) s_last = (atomicAdd(&g_done2, 1u) == GRID_T - 1);
    __syncthreads();
    if (!s_last) return;

    // ---- final mean + full state reset (last block only) ----
    if (t == 0) {
        double outv;
        if (p01p1 == 0u) {
            outv = __ldcg(&g_sumHi) / (double)NPIX;   // fallback: plain mean
        } else {
            unsigned k2 = __ldcg(&g_k2);
            unsigned cum = 0;
            double ssum = 0.0;
            for (int bbin = 255; bbin >= 0; bbin--) {
                unsigned c = __ldcg(&g_cnt2[bbin]);
                ssum += (double)__ldcg(&g_sum2[bbin]);
                cum  += c;
                if (cum >= k2) break;        // threshold byte reached (ties kept)
            }
            double   ktot = __ldcg(&g_sumHi) + ssum;
            unsigned kcnt = __ldcg(&g_cntHi) + cum;
            if (kcnt == 0) kcnt = 1;
            outv = ktot / (double)kcnt;
        }
        out[0] = (float)outv;
    }
    __syncthreads();
    for (int i = t; i < 4096; i += TB) g_hist1[i] = 0;
    for (int i = t; i < 256;  i += TB) { g_cnt2[i] = 0; g_sum2[i] = 0.f; }
    if (t == 0) {
        g_sumHi = 0.0; g_cntHi = 0;
        g_pref0p1 = 0; g_pref01p1 = 0; g_k1 = 0; g_k2 = 0;
        g_done1 = 0; g_done2 = 0; g_flag1 = 0; g_ccount = 0;
        __threadfence();
    }
}

// ------------------------------------------------------------------
extern "C" void kernel_launch(void* const* d_in, const int* in_sizes, int n_in,
                              void* d_out, int out_size) {
    const float* logits = (const float*)d_in[0];
    const void*  tgt    = d_in[1];
    float* out = (float*)d_out;

    k_loss <<<GRID_L, TB>>>(logits, tgt);
    k_tail <<<GRID_T, TB>>>(out);
}

// round 16
// speedup vs baseline: 1.2261x; 1.2261x over previous
#include <cuda_runtime.h>

#define NCLS 19
#define HW_   (512*1024)        // 2^19
#define NPIX  (4*HW_)           // 2,097,152
#define GRIDB 1184              // R1's grid: 8 CTA/SM nominal
#define TB    256
#define INV   0xFFFFFFFFu

// ---- static scratch (zero-init at load; each consumer self-cleans) ----
__device__ float    g_loss[NPIX];        // 8 MB
__device__ unsigned g_hist0[4096];
__device__ unsigned g_hist1[4096];
__device__ unsigned g_hist2[256];
__device__ double   g_sum;
__device__ unsigned g_cnt;
__device__ unsigned g_pref0p1, g_pref01p1, g_k1, g_k2;   // prefix+1; 0 = invalid
__device__ unsigned g_tbits, g_tvalid;                   // threshold bits + valid
__device__ unsigned g_done0, g_done1, g_done2, g_done3;

// ------------------------------------------------------------------
// Descending scan over a 4096-bin histogram; winning thread writes the
// (bin, rank) into shared outputs. 256 threads, 16 bins each.
__device__ void scan4096(const unsigned* __restrict__ hist, unsigned k,
                         unsigned* ss, unsigned* out_bin, unsigned* out_r,
                         bool derive_k) {
    int t = threadIdx.x;
    unsigned cnt[16]; unsigned myv = 0;
    #pragma unroll
    for (int i = 0; i < 16; i++) { cnt[i] = __ldcg(&hist[4095 - (t * 16 + i)]); myv += cnt[i]; }
    ss[t] = myv; __syncthreads();
    for (int off = 1; off < 256; off <<= 1) {
        unsigned x = (t >= off) ? ss[t - off] : 0u;
        __syncthreads(); ss[t] += x; __syncthreads();
    }
    if (derive_k) {
        unsigned total = ss[255];          // uniform
        if (total == 0) return;            // *out_bin stays INV
        unsigned nk = (unsigned)(0.7f * (float)total);
        if (nk < 100000u) nk = 100000u;
        if (nk > total)   nk = total;
        k = nk;
    }
    unsigned hi = ss[t], lo = hi - myv;
    if (k > lo && k <= hi) {               // exactly one thread wins
        unsigned cum = lo;
        #pragma unroll
        for (int i = 0; i < 16; i++) {
            cum += cnt[i];
            if (k <= cum) {
                *out_bin = 4095u - (t * 16 + i);
                *out_r   = k - (cum - cnt[i]);
                break;
            }
        }
    }
}

// ------------------------------------------------------------------
// Pass A: R1's loss kernel (v[19] batched loads, grid 1184, no bounds cap)
// + hist0; last block fuses scan0 and self-cleans.
__global__ void k_loss(const float* __restrict__ logits,
                       const void* __restrict__ tgt_raw) {
    __shared__ unsigned sh[4096];
    __shared__ unsigned s_ss[256];
    __shared__ unsigned s_bin, s_r;
    __shared__ bool     s_last;
    int t = threadIdx.x;
    for (int i = t; i < 4096; i += TB) sh[i] = 0;
    __syncthreads();

    // dtype detection (uniform, cached)
    const long long* tdet = (const long long*)tgt_raw;
    int tmode = 1;
    #pragma unroll
    for (int i = 0; i < 8; i++) {
        long long x = tdet[i];
        if (x < 0 || x >= (long long)NCLS) tmode = 0;
    }
    const long long* t64 = (const long long*)tgt_raw;
    const int*       t32 = (const int*)tgt_raw;

    int stride = GRIDB * TB;
    for (int p = blockIdx.x * TB + t; p < NPIX; p += stride) {
        int n  = p >> 19;
        int hw = p & (HW_ - 1);
        const float* base = logits + (size_t)n * (NCLS * (size_t)HW_) + hw;
        int tt = tmode ? (int)__ldg(t64 + p) : __ldg(t32 + p);

        float v[NCLS];                     // 19 independent loads, batched
        #pragma unroll
        for (int c = 0; c < NCLS; c++) v[c] = __ldg(base + (size_t)c * HW_);
        float xt = __ldg(base + (size_t)tt * HW_);   // gather: L1/L2 hit

        float s = 0.f;
        #pragma unroll
        for (int c = 0; c < NCLS; c++) s += __expf(v[c]);

        float l = __logf(s) - xt;
        g_loss[p] = l;
        if (l > 0.f) atomicAdd(&sh[__float_as_uint(l) >> 20], 1u);
    }
    __syncthreads();
    for (int i = t; i < 4096; i += TB) {
        unsigned c = sh[i];
        if (c) atomicAdd(&g_hist0[i], c);
    }
    __threadfence();
    __syncthreads();                        // all hist0 atomics issued
    if (t == 0) s_last = (atomicAdd(&g_done0, 1u) == GRIDB - 1);
    __syncthreads();
    if (!s_last) return;

    // ---- fused scan0 (last block) + self-clean ----
    if (t == 0) { s_bin = INV; s_r = 0; }
    __syncthreads();
    scan4096(g_hist0, 0, s_ss, &s_bin, &s_r, true);
    __syncthreads();
    if (t == 0 && s_bin != INV) { g_pref0p1 = s_bin + 1u; g_k1 = s_r; }
    for (int i = t; i < 4096; i += TB) g_hist0[i] = 0;
    if (t == 0) g_done0 = 0;
}

// ------------------------------------------------------------------
// Pass B: R1's hist1 (grid 1184, scalar strided loop, 11.7us measured);
// last block fuses scan1 + self-clean.
__global__ void k_hist1() {
    __shared__ unsigned sh[4096];
    __shared__ unsigned s_ss[256];
    __shared__ unsigned s_bin, s_r;
    __shared__ bool     s_last;
    int t = threadIdx.x;
    for (int i = t; i < 4096; i += TB) sh[i] = 0;
    __syncthreads();

    unsigned p0p1 = g_pref0p1;
    const unsigned* lb = (const unsigned*)g_loss;
    int stride = GRIDB * TB;
    if (p0p1 != 0u) {
        unsigned pref0 = p0p1 - 1u;
        for (int p = blockIdx.x * TB + t; p < NPIX; p += stride) {
            unsigned b = __ldg(lb + p);
            if ((int)b > 0 && (b >> 20) == pref0) atomicAdd(&sh[(b >> 8) & 0xFFFu], 1u);
        }
        __syncthreads();
        for (int i = t; i < 4096; i += TB) {
            unsigned c = sh[i];
            if (c) atomicAdd(&g_hist1[i], c);
        }
    }
    __threadfence();
    __syncthreads();                        // all hist1 atomics issued
    if (t == 0) s_last = (atomicAdd(&g_done1, 1u) == GRIDB - 1);
    __syncthreads();
    if (!s_last) return;

    // ---- fused scan1 (last block) + self-clean ----
    if (p0p1 != 0u) {
        if (t == 0) { s_bin = INV; s_r = 0; }
        __syncthreads();
        scan4096(g_hist1, __ldcg(&g_k1), s_ss, &s_bin, &s_r, false);
        __syncthreads();
        if (t == 0 && s_bin != INV) {
            g_pref01p1 = (((p0p1 - 1u) << 12) | s_bin) + 1u;
            g_k2 = s_r;
        }
    }
    for (int i = t; i < 4096; i += TB) g_hist1[i] = 0;
    if (t == 0) g_done1 = 0;
}

// ------------------------------------------------------------------
// Pass C: R1's hist2 (direct global atomics; hits are rare — only the
// selected 24-bit prefix); last block fuses the 256-bin scan -> threshold,
// zeroes hist2.
__global__ void k_hist2() {
    __shared__ unsigned s_h[256];
    __shared__ bool     s_last;
    int t = threadIdx.x;

    unsigned p01p1 = g_pref01p1;
    const unsigned* lb = (const unsigned*)g_loss;
    int stride = GRIDB * TB;
    if (p01p1 != 0u) {
        unsigned pref01 = p01p1 - 1u;
        for (int p = blockIdx.x * TB + t; p < NPIX; p += stride) {
            unsigned b = __ldg(lb + p);
            if ((int)b > 0 && (b >> 8) == pref01) atomicAdd(&g_hist2[b & 0xFFu], 1u);
        }
    }
    __threadfence();
    __syncthreads();                        // all hist2 atomics issued
    if (t == 0) s_last = (atomicAdd(&g_done2, 1u) == GRIDB - 1);
    __syncthreads();
    if (!s_last) return;

    // ---- fused scan2 (last block): find threshold byte ----
    s_h[t] = __ldcg(&g_hist2[t]);
    __syncthreads();
    if (t == 0 && p01p1 != 0u) {
        unsigned pref01 = p01p1 - 1u;
        unsigned k2 = __ldcg(&g_k2);
        unsigned cum = 0;
        for (int b = 255; b >= 0; b--) {
            cum += s_h[b];
            if (cum >= k2) {
                g_tbits  = (pref01 << 8) | (unsigned)b;
                g_tvalid = 1u;
                break;
            }
        }
    }
    g_hist2[t] = 0;
    if (t == 0) g_done2 = 0;
}

// ------------------------------------------------------------------
// Pass D: R1's reduce (l >= thresh, double tree) + fused final + full reset.
__global__ void k_reduce(float* __restrict__ out) {
    __shared__ double   s_rd[256];
    __shared__ unsigned s_rc[256];
    __shared__ bool     s_last;
    int t = threadIdx.x;

    float th = g_tvalid ? __uint_as_float(g_tbits)
                        : __int_as_float(0xFF800000);   // -inf: keep all (fallback)
    double s = 0.0; unsigned c = 0;
    int stride = GRIDB * TB;
    for (int p = blockIdx.x * TB + t; p < NPIX; p += stride) {
        float l = __ldg(&g_loss[p]);
        if (l >= th) { s += (double)l; c++; }
    }
    s_rd[t] = s; s_rc[t] = c;
    __syncthreads();
    for (int off = 128; off > 0; off >>= 1) {
        if (t < off) { s_rd[t] += s_rd[t + off]; s_rc[t] += s_rc[t + off]; }
        __syncthreads();
    }
    if (t == 0) {
        atomicAdd(&g_sum, s_rd[0]);
        atomicAdd(&g_cnt, s_rc[0]);
    }
    __threadfence();
    __syncthreads();                        // block's adds issued
    if (t == 0) s_last = (atomicAdd(&g_done3, 1u) == GRIDB - 1);
    __syncthreads();
    if (!s_last) return;

    // ---- fused final + full state reset (last block only) ----
    if (t == 0) {
        unsigned kc = __ldcg(&g_cnt);
        if (kc == 0) kc = 1;
        out[0] = (float)(__ldcg(&g_sum) / (double)kc);
        // reset everything for next graph replay
        g_sum = 0.0; g_cnt = 0;
        g_pref0p1 = 0; g_pref01p1 = 0; g_k1 = 0; g_k2 = 0;
        g_tbits = 0; g_tvalid = 0;
        g_done3 = 0;
        __threadfence();
    }
}

// ------------------------------------------------------------------
extern "C" void kernel_launch(void* const* d_in, const int* in_sizes, int n_in,
                              void* d_out, int out_size) {
    const float* logits = (const float*)d_in[0];
    const void*  tgt    = d_in[1];
    float* out = (float*)d_out;

    k_loss  <<<GRIDB, TB>>>(logits, tgt);
    k_hist1 <<<GRIDB, TB>>>();
    k_hist2 <<<GRIDB, TB>>>();
    k_reduce<<<GRIDB, TB>>>(out);
}